// round 4
// baseline (speedup 1.0000x reference)
#include <cuda_runtime.h>

#define Dd 96
#define Hh 160
#define Ww 160
#define DHW (Dd*Hh*Ww)

// scratch: packed composed-flow fields: float2 (z,y) + float plane (x)
__device__ float2 g_A2[DHW];
__device__ float  g_A1[DHW];
__device__ float2 g_B2[DHW];
__device__ float  g_B1[DHW];

// coord(v,s) = v*s/(s-1) - 0.5  (normalize_grid + grid_sample denorm, fused)
#define SZC ((float)Dd / (float)(Dd - 1))
#define SYC ((float)Hh / (float)(Hh - 1))
#define SXC ((float)Ww / (float)(Ww - 1))

__device__ __forceinline__ void make_corners(float cz, float cy, float cx,
                                             int off[8], float w[8]) {
    float z0f = floorf(cz), y0f = floorf(cy), x0f = floorf(cx);
    float tz = cz - z0f, ty = cy - y0f, tx = cx - x0f;
    int z0 = (int)z0f, y0 = (int)y0f, x0 = (int)x0f;
    int z1 = z0 + 1,  y1 = y0 + 1,  x1 = x0 + 1;

    float wz0 = (z0 >= 0 && z0 < Dd) ? (1.f - tz) : 0.f;
    float wz1 = (z1 >= 0 && z1 < Dd) ? tz         : 0.f;
    float wy0 = (y0 >= 0 && y0 < Hh) ? (1.f - ty) : 0.f;
    float wy1 = (y1 >= 0 && y1 < Hh) ? ty         : 0.f;
    float wx0 = (x0 >= 0 && x0 < Ww) ? (1.f - tx) : 0.f;
    float wx1 = (x1 >= 0 && x1 < Ww) ? tx         : 0.f;

    int z0c = min(max(z0, 0), Dd - 1), z1c = min(max(z1, 0), Dd - 1);
    int y0c = min(max(y0, 0), Hh - 1), y1c = min(max(y1, 0), Hh - 1);
    int x0c = min(max(x0, 0), Ww - 1), x1c = min(max(x1, 0), Ww - 1);

    int b00 = (z0c * Hh + y0c) * Ww;
    int b01 = (z0c * Hh + y1c) * Ww;
    int b10 = (z1c * Hh + y0c) * Ww;
    int b11 = (z1c * Hh + y1c) * Ww;

    off[0] = b00 + x0c;  w[0] = wz0 * wy0 * wx0;
    off[1] = b00 + x1c;  w[1] = wz0 * wy0 * wx1;
    off[2] = b01 + x0c;  w[2] = wz0 * wy1 * wx0;
    off[3] = b01 + x1c;  w[3] = wz0 * wy1 * wx1;
    off[4] = b10 + x0c;  w[4] = wz1 * wy0 * wx0;
    off[5] = b10 + x1c;  w[5] = wz1 * wy0 * wx1;
    off[6] = b11 + x0c;  w[6] = wz1 * wy1 * wx0;
    off[7] = b11 + x1c;  w[7] = wz1 * wy1 * wx1;
}

__device__ __forceinline__ void tile_coords(int& x, int& y, int& z, int& idx) {
    x = blockIdx.x * 32 + threadIdx.x;
    y = blockIdx.y * 8 + threadIdx.y;
    z = blockIdx.z;
    idx = (z * Hh + y) * Ww + x;
}

__device__ __forceinline__ void coord_from_flow(int x, int y, int z, float rf,
                                                float fz, float fy, float fx,
                                                float& cz, float& cy, float& cx) {
    cz = fmaf(fz * rf, SZC, (float)z * SZC - 0.5f);
    cy = fmaf(fy * rf, SYC, (float)y * SYC - 0.5f);
    cx = fmaf(fx * rf, SXC, (float)x * SXC - 0.5f);
}

// Batched gather of packed field: issue all 16 loads first, then FMA.
__device__ __forceinline__ void gather_packed_batched(
        const float2* __restrict__ p2, const float* __restrict__ p1,
        const int off[8], const float w[8],
        float& vz, float& vy, float& vx) {
    float2 a[8]; float b[8];
    #pragma unroll
    for (int k = 0; k < 8; k++) a[k] = __ldg(p2 + off[k]);
    #pragma unroll
    for (int k = 0; k < 8; k++) b[k] = __ldg(p1 + off[k]);

    float vz0 = 0.f, vz1 = 0.f, vy0 = 0.f, vy1 = 0.f, vx0 = 0.f, vx1 = 0.f;
    #pragma unroll
    for (int k = 0; k < 8; k += 2) {
        vz0 = fmaf(w[k],   a[k].x,   vz0);
        vz1 = fmaf(w[k+1], a[k+1].x, vz1);
        vy0 = fmaf(w[k],   a[k].y,   vy0);
        vy1 = fmaf(w[k+1], a[k+1].y, vy1);
        vx0 = fmaf(w[k],   b[k],     vx0);
        vx1 = fmaf(w[k+1], b[k+1],   vx1);
    }
    vz = vz0 + vz1; vy = vy0 + vy1; vx = vx0 + vx1;
}

// Step 1: comp PLANAR (flow_list[0]); all 24 loads batched; output packed.
__global__ void __launch_bounds__(256, 3)
step_planar(const float* __restrict__ comp, const float* __restrict__ dvf,
            float2* __restrict__ o2, float* __restrict__ o1,
            const float* __restrict__ rfp) {
    int x, y, z, idx; tile_coords(x, y, z, idx);
    float rf = __ldg(rfp);

    float fz = dvf[idx], fy = dvf[idx + DHW], fx = dvf[idx + 2 * DHW];
    float cz, cy, cx; coord_from_flow(x, y, z, rf, fz, fy, fx, cz, cy, cx);

    int off[8]; float w[8];
    make_corners(cz, cy, cx, off, w);

    const float* cpz = comp;
    const float* cpy = comp + DHW;
    const float* cpx = comp + 2 * DHW;

    float vzv[8], vyv[8], vxv[8];
    #pragma unroll
    for (int k = 0; k < 8; k++) vzv[k] = __ldg(cpz + off[k]);
    #pragma unroll
    for (int k = 0; k < 8; k++) vyv[k] = __ldg(cpy + off[k]);
    #pragma unroll
    for (int k = 0; k < 8; k++) vxv[k] = __ldg(cpx + off[k]);

    float vz0=0.f, vz1=0.f, vy0=0.f, vy1=0.f, vx0=0.f, vx1=0.f;
    #pragma unroll
    for (int k = 0; k < 8; k += 2) {
        vz0 = fmaf(w[k], vzv[k], vz0);   vz1 = fmaf(w[k+1], vzv[k+1], vz1);
        vy0 = fmaf(w[k], vyv[k], vy0);   vy1 = fmaf(w[k+1], vyv[k+1], vy1);
        vx0 = fmaf(w[k], vxv[k], vx0);   vx1 = fmaf(w[k+1], vxv[k+1], vx1);
    }

    o2[idx] = make_float2(vz0 + vz1 + fz, vy0 + vy1 + fy);
    o1[idx] = vx0 + vx1 + fx;
}

// Step 2: comp packed; batched loads; output packed.
__global__ void __launch_bounds__(256, 3)
step_packed(const float2* __restrict__ c2, const float* __restrict__ c1,
            const float* __restrict__ dvf,
            float2* __restrict__ o2, float* __restrict__ o1,
            const float* __restrict__ rfp) {
    int x, y, z, idx; tile_coords(x, y, z, idx);
    float rf = __ldg(rfp);

    float fz = dvf[idx], fy = dvf[idx + DHW], fx = dvf[idx + 2 * DHW];
    float cz, cy, cx; coord_from_flow(x, y, z, rf, fz, fy, fx, cz, cy, cx);

    int off[8]; float w[8];
    make_corners(cz, cy, cx, off, w);

    float vz, vy, vx;
    gather_packed_batched(c2, c1, off, w, vz, vy, vx);

    o2[idx] = make_float2(vz + fz, vy + fy);
    o1[idx] = vx + fx;
}

// Final fused: composed3 = trilerp(comp, base+ff*rf) + ff -> out_flow planar
//              deform    = trilerp(src,  base+composed3*rf)
__global__ void __launch_bounds__(256, 3)
warp_final(const float2* __restrict__ c2, const float* __restrict__ c1,
           const float* __restrict__ ff, const float* __restrict__ src,
           float* __restrict__ out_deform, float* __restrict__ out_flow,
           const float* __restrict__ rfp) {
    int x, y, z, idx; tile_coords(x, y, z, idx);
    float rf = __ldg(rfp);

    float fz = ff[idx], fy = ff[idx + DHW], fx = ff[idx + 2 * DHW];
    float cz, cy, cx; coord_from_flow(x, y, z, rf, fz, fy, fx, cz, cy, cx);

    int off[8]; float w[8];
    make_corners(cz, cy, cx, off, w);

    float vz, vy, vx;
    gather_packed_batched(c2, c1, off, w, vz, vy, vx);

    float coz = vz + fz, coy = vy + fy, cox = vx + fx;
    out_flow[idx]           = coz;
    out_flow[idx + DHW]     = coy;
    out_flow[idx + 2 * DHW] = cox;

    float cz2, cy2, cx2; coord_from_flow(x, y, z, rf, coz, coy, cox, cz2, cy2, cx2);

    int off2[8]; float w2[8];
    make_corners(cz2, cy2, cx2, off2, w2);

    float sv[8];
    #pragma unroll
    for (int k = 0; k < 8; k++) sv[k] = __ldg(src + off2[k]);
    float s0 = 0.f, s1 = 0.f;
    #pragma unroll
    for (int k = 0; k < 8; k += 2) {
        s0 = fmaf(w2[k], sv[k], s0);
        s1 = fmaf(w2[k+1], sv[k+1], s1);
    }
    out_deform[idx] = s0 + s1;
}

extern "C" void kernel_launch(void* const* d_in, const int* in_sizes, int n_in,
                              void* d_out, int out_size) {
    const float* src        = (const float*)d_in[0];   // [1,1,D,H,W]
    const float* flow_list  = (const float*)d_in[1];   // [3,1,3,D,H,W]
    const float* final_flow = (const float*)d_in[2];   // [1,3,D,H,W]
    const float* rfp        = (const float*)d_in[3];   // scalar

    float* out_deform = (float*)d_out;          // [D*H*W]
    float* out_flow   = (float*)d_out + DHW;    // [3*D*H*W]

    float2 *A2, *B2; float *A1, *B1;
    cudaGetSymbolAddress((void**)&A2, g_A2);
    cudaGetSymbolAddress((void**)&A1, g_A1);
    cudaGetSymbolAddress((void**)&B2, g_B2);
    cudaGetSymbolAddress((void**)&B1, g_B1);

    dim3 block(32, 8, 1);
    dim3 grid(Ww / 32, Hh / 8, Dd);

    // iter 1: comp = flow_list[0] (planar), dvf = flow_list[1] -> packed A
    step_planar<<<grid, block>>>(flow_list, flow_list + 3 * DHW, A2, A1, rfp);
    // iter 2: comp = A (packed), dvf = flow_list[2] -> packed B
    step_packed<<<grid, block>>>(A2, A1, flow_list + 6 * DHW, B2, B1, rfp);
    // iter 3 + final src sample fused
    warp_final<<<grid, block>>>(B2, B1, final_flow, src, out_deform, out_flow, rfp);
}

// round 5
// speedup vs baseline: 1.0249x; 1.0249x over previous
#include <cuda_runtime.h>

#define Dd 96
#define Hh 160
#define Ww 160
#define DHW (Dd*Hh*Ww)

// scratch: packed composed-flow fields: float2 (z,y) + float plane (x)
__device__ float2 g_A2[DHW];
__device__ float  g_A1[DHW];
__device__ float2 g_B2[DHW];
__device__ float  g_B1[DHW];

// coord(v,s) = v*s/(s-1) - 0.5  (normalize_grid + grid_sample denorm, fused)
#define SZC ((float)Dd / (float)(Dd - 1))
#define SYC ((float)Hh / (float)(Hh - 1))
#define SXC ((float)Ww / (float)(Ww - 1))

__device__ __forceinline__ void make_corners(float cz, float cy, float cx,
                                             int off[8], float w[8]) {
    float z0f = floorf(cz), y0f = floorf(cy), x0f = floorf(cx);
    float tz = cz - z0f, ty = cy - y0f, tx = cx - x0f;
    int z0 = (int)z0f, y0 = (int)y0f, x0 = (int)x0f;
    int z1 = z0 + 1,  y1 = y0 + 1,  x1 = x0 + 1;

    float wz0 = (z0 >= 0 && z0 < Dd) ? (1.f - tz) : 0.f;
    float wz1 = (z1 >= 0 && z1 < Dd) ? tz         : 0.f;
    float wy0 = (y0 >= 0 && y0 < Hh) ? (1.f - ty) : 0.f;
    float wy1 = (y1 >= 0 && y1 < Hh) ? ty         : 0.f;
    float wx0 = (x0 >= 0 && x0 < Ww) ? (1.f - tx) : 0.f;
    float wx1 = (x1 >= 0 && x1 < Ww) ? tx         : 0.f;

    int z0c = min(max(z0, 0), Dd - 1), z1c = min(max(z1, 0), Dd - 1);
    int y0c = min(max(y0, 0), Hh - 1), y1c = min(max(y1, 0), Hh - 1);
    int x0c = min(max(x0, 0), Ww - 1), x1c = min(max(x1, 0), Ww - 1);

    int b00 = (z0c * Hh + y0c) * Ww;
    int b01 = (z0c * Hh + y1c) * Ww;
    int b10 = (z1c * Hh + y0c) * Ww;
    int b11 = (z1c * Hh + y1c) * Ww;

    off[0] = b00 + x0c;  w[0] = wz0 * wy0 * wx0;
    off[1] = b00 + x1c;  w[1] = wz0 * wy0 * wx1;
    off[2] = b01 + x0c;  w[2] = wz0 * wy1 * wx0;
    off[3] = b01 + x1c;  w[3] = wz0 * wy1 * wx1;
    off[4] = b10 + x0c;  w[4] = wz1 * wy0 * wx0;
    off[5] = b10 + x1c;  w[5] = wz1 * wy0 * wx1;
    off[6] = b11 + x0c;  w[6] = wz1 * wy1 * wx0;
    off[7] = b11 + x1c;  w[7] = wz1 * wy1 * wx1;
}

__device__ __forceinline__ void coord_from_flow(int x, int y, int z, float rf,
                                                float fz, float fy, float fx,
                                                float& cz, float& cy, float& cx) {
    cz = fmaf(fz * rf, SZC, (float)z * SZC - 0.5f);
    cy = fmaf(fy * rf, SYC, (float)y * SYC - 0.5f);
    cx = fmaf(fx * rf, SXC, (float)x * SXC - 0.5f);
}

// Gather packed field trilinearly for one voxel.
__device__ __forceinline__ void gather_packed(const float2* __restrict__ p2,
                                              const float* __restrict__ p1,
                                              float cz, float cy, float cx,
                                              float& vz, float& vy, float& vx) {
    int off[8]; float w[8];
    make_corners(cz, cy, cx, off, w);
    vz = 0.f; vy = 0.f; vx = 0.f;
    #pragma unroll
    for (int k = 0; k < 8; k++) {
        float2 v = __ldg(p2 + off[k]);
        vz = fmaf(w[k], v.x, vz);
        vy = fmaf(w[k], v.y, vy);
        vx = fmaf(w[k], __ldg(p1 + off[k]), vx);
    }
}

// Gather planar 3-channel field for one voxel.
__device__ __forceinline__ void gather_planar(const float* __restrict__ comp,
                                              float cz, float cy, float cx,
                                              float& vz, float& vy, float& vx) {
    int off[8]; float w[8];
    make_corners(cz, cy, cx, off, w);
    vz = 0.f; vy = 0.f; vx = 0.f;
    const float* cpy = comp + DHW;
    const float* cpx = comp + 2 * DHW;
    #pragma unroll
    for (int k = 0; k < 8; k++) {
        vz = fmaf(w[k], __ldg(comp + off[k]), vz);
        vy = fmaf(w[k], __ldg(cpy + off[k]), vy);
        vx = fmaf(w[k], __ldg(cpx + off[k]), vx);
    }
}

// 2 voxels per thread along x. block (16,16,1), grid (W/32, H/16, D).
__device__ __forceinline__ void pair_coords(int& x, int& y, int& z, int& idx) {
    x = blockIdx.x * 32 + threadIdx.x * 2;
    y = blockIdx.y * 16 + threadIdx.y;
    z = blockIdx.z;
    idx = (z * Hh + y) * Ww + x;
}

// Step 1: comp PLANAR (flow_list[0]); dvf planar; output packed. 2 voxels/thread.
__global__ void __launch_bounds__(256)
step_planar(const float* __restrict__ comp, const float* __restrict__ dvf,
            float2* __restrict__ o2, float* __restrict__ o1,
            const float* __restrict__ rfp) {
    int x, y, z, idx; pair_coords(x, y, z, idx);
    float rf = __ldg(rfp);

    float2 fzp = *(const float2*)(dvf + idx);
    float2 fyp = *(const float2*)(dvf + idx + DHW);
    float2 fxp = *(const float2*)(dvf + idx + 2 * DHW);

    float cz, cy, cx, vz, vy, vx;

    coord_from_flow(x, y, z, rf, fzp.x, fyp.x, fxp.x, cz, cy, cx);
    gather_planar(comp, cz, cy, cx, vz, vy, vx);
    float az = vz + fzp.x, ay = vy + fyp.x, ax = vx + fxp.x;

    coord_from_flow(x + 1, y, z, rf, fzp.y, fyp.y, fxp.y, cz, cy, cx);
    gather_planar(comp, cz, cy, cx, vz, vy, vx);
    float bz = vz + fzp.y, by = vy + fyp.y, bx = vx + fxp.y;

    *(float4*)(o2 + idx) = make_float4(az, ay, bz, by);
    *(float2*)(o1 + idx) = make_float2(ax, bx);
}

// Step 2: comp packed; dvf planar; output packed. 2 voxels/thread.
__global__ void __launch_bounds__(256)
step_packed(const float2* __restrict__ c2, const float* __restrict__ c1,
            const float* __restrict__ dvf,
            float2* __restrict__ o2, float* __restrict__ o1,
            const float* __restrict__ rfp) {
    int x, y, z, idx; pair_coords(x, y, z, idx);
    float rf = __ldg(rfp);

    float2 fzp = *(const float2*)(dvf + idx);
    float2 fyp = *(const float2*)(dvf + idx + DHW);
    float2 fxp = *(const float2*)(dvf + idx + 2 * DHW);

    float cz, cy, cx, vz, vy, vx;

    coord_from_flow(x, y, z, rf, fzp.x, fyp.x, fxp.x, cz, cy, cx);
    gather_packed(c2, c1, cz, cy, cx, vz, vy, vx);
    float az = vz + fzp.x, ay = vy + fyp.x, ax = vx + fxp.x;

    coord_from_flow(x + 1, y, z, rf, fzp.y, fyp.y, fxp.y, cz, cy, cx);
    gather_packed(c2, c1, cz, cy, cx, vz, vy, vx);
    float bz = vz + fzp.y, by = vy + fyp.y, bx = vx + fxp.y;

    *(float4*)(o2 + idx) = make_float4(az, ay, bz, by);
    *(float2*)(o1 + idx) = make_float2(ax, bx);
}

// Final fused: composed3 -> out_flow planar; deform = trilerp(src, ...). 2 voxels/thread.
__global__ void __launch_bounds__(256)
warp_final(const float2* __restrict__ c2, const float* __restrict__ c1,
           const float* __restrict__ ff, const float* __restrict__ src,
           float* __restrict__ out_deform, float* __restrict__ out_flow,
           const float* __restrict__ rfp) {
    int x, y, z, idx; pair_coords(x, y, z, idx);
    float rf = __ldg(rfp);

    float2 fzp = *(const float2*)(ff + idx);
    float2 fyp = *(const float2*)(ff + idx + DHW);
    float2 fxp = *(const float2*)(ff + idx + 2 * DHW);

    float cz, cy, cx, vz, vy, vx;

    coord_from_flow(x, y, z, rf, fzp.x, fyp.x, fxp.x, cz, cy, cx);
    gather_packed(c2, c1, cz, cy, cx, vz, vy, vx);
    float az = vz + fzp.x, ay = vy + fyp.x, ax = vx + fxp.x;

    coord_from_flow(x + 1, y, z, rf, fzp.y, fyp.y, fxp.y, cz, cy, cx);
    gather_packed(c2, c1, cz, cy, cx, vz, vy, vx);
    float bz = vz + fzp.y, by = vy + fyp.y, bx = vx + fxp.y;

    *(float2*)(out_flow + idx)            = make_float2(az, bz);
    *(float2*)(out_flow + idx + DHW)      = make_float2(ay, by);
    *(float2*)(out_flow + idx + 2 * DHW)  = make_float2(ax, bx);

    // second sample: src at base + composed3*rf
    float sA, sB;
    {
        float c2z, c2y, c2x; coord_from_flow(x, y, z, rf, az, ay, ax, c2z, c2y, c2x);
        int off[8]; float w[8];
        make_corners(c2z, c2y, c2x, off, w);
        float s = 0.f;
        #pragma unroll
        for (int k = 0; k < 8; k++) s = fmaf(w[k], __ldg(src + off[k]), s);
        sA = s;
    }
    {
        float c2z, c2y, c2x; coord_from_flow(x + 1, y, z, rf, bz, by, bx, c2z, c2y, c2x);
        int off[8]; float w[8];
        make_corners(c2z, c2y, c2x, off, w);
        float s = 0.f;
        #pragma unroll
        for (int k = 0; k < 8; k++) s = fmaf(w[k], __ldg(src + off[k]), s);
        sB = s;
    }
    *(float2*)(out_deform + idx) = make_float2(sA, sB);
}

extern "C" void kernel_launch(void* const* d_in, const int* in_sizes, int n_in,
                              void* d_out, int out_size) {
    const float* src        = (const float*)d_in[0];   // [1,1,D,H,W]
    const float* flow_list  = (const float*)d_in[1];   // [3,1,3,D,H,W]
    const float* final_flow = (const float*)d_in[2];   // [1,3,D,H,W]
    const float* rfp        = (const float*)d_in[3];   // scalar

    float* out_deform = (float*)d_out;          // [D*H*W]
    float* out_flow   = (float*)d_out + DHW;    // [3*D*H*W]

    float2 *A2, *B2; float *A1, *B1;
    cudaGetSymbolAddress((void**)&A2, g_A2);
    cudaGetSymbolAddress((void**)&A1, g_A1);
    cudaGetSymbolAddress((void**)&B2, g_B2);
    cudaGetSymbolAddress((void**)&B1, g_B1);

    dim3 block(16, 16, 1);
    dim3 grid(Ww / 32, Hh / 16, Dd);

    // iter 1: comp = flow_list[0] (planar), dvf = flow_list[1] -> packed A
    step_planar<<<grid, block>>>(flow_list, flow_list + 3 * DHW, A2, A1, rfp);
    // iter 2: comp = A (packed), dvf = flow_list[2] -> packed B
    step_packed<<<grid, block>>>(A2, A1, flow_list + 6 * DHW, B2, B1, rfp);
    // iter 3 + final src sample fused
    warp_final<<<grid, block>>>(B2, B1, final_flow, src, out_deform, out_flow, rfp);
}